// round 17
// baseline (speedup 1.0000x reference)
#include <cuda_runtime.h>

// Problem constants
#define HDIM   512
#define BATCH  2
#define SEQ    128
#define DSRC   768
#define NTOK   (BATCH * SEQ)   // 256
#define NITER  30
#define BSZ    32              // sorted-block size (elements)
#define NBLK   (HDIM / BSZ)    // 16 blocks
#define NPAIR  (BSZ / 2)       // 16 packed pairs per block
#define NSM    148             // persistent sinkhorn grid

// -(SCALE/REG) * log2(e) = -5000 * 1.4426950408889634
#define NEGC  (-7213.4752044448170f)
#define CPOS  (7213.4752044448170f)
// -log2(H)
#define LOGMARG2 (-9.0f)
// cutoff: drop terms with tau < -TW (rel_err empirically invariant 60->24)
#define TW 24.0f

typedef unsigned long long ull;

// Scratch (static device globals; no runtime allocation allowed)
__device__ float g_srcA[NTOK * HDIM];           // K-half 0 partial
__device__ float g_srcB[NTOK * HDIM];           // K-half 1 partial
__device__ float g_sumP[BATCH * HDIM * HDIM];   // 2 MB
__device__ int   g_counter;                     // persistent token counter

__device__ __forceinline__ float ex2(float x) {
    float y; asm("ex2.approx.f32 %0, %1;" : "=f"(y) : "f"(x)); return y;
}
__device__ __forceinline__ float lg2(float x) {
    float y; asm("lg2.approx.f32 %0, %1;" : "=f"(y) : "f"(x)); return y;
}
__device__ __forceinline__ ull pack2(float lo, float hi) {
    ull r; asm("mov.b64 %0, {%1, %2};" : "=l"(r) : "f"(lo), "f"(hi)); return r;
}
__device__ __forceinline__ void unpack2(ull v, float& lo, float& hi) {
    asm("mov.b64 {%0, %1}, %2;" : "=f"(lo), "=f"(hi) : "l"(v));
}
__device__ __forceinline__ ull subx2(ull a, ull b) {
    ull r; asm("sub.rn.f32x2 %0, %1, %2;" : "=l"(r) : "l"(a), "l"(b)); return r;
}
__device__ __forceinline__ ull addx2(ull a, ull b) {
    ull r; asm("add.rn.f32x2 %0, %1, %2;" : "=l"(r) : "l"(a), "l"(b)); return r;
}
__device__ __forceinline__ ull mulx2(ull a, ull b) {
    ull r; asm("mul.rn.f32x2 %0, %1, %2;" : "=l"(r) : "l"(a), "l"(b)); return r;
}
__device__ __forceinline__ ull fmax2p(ull a, ull b, ull c) {
    ull r; asm("fma.rn.f32x2 %0, %1, %2, %3;" : "=l"(r) : "l"(a), "l"(b), "l"(c)); return r;
}
// warp-wide f32 max via monotone-uint mapping + int redux (sm_80+)
__device__ __forceinline__ float warp_max_f32(float x) {
    unsigned b = __float_as_uint(x);
    unsigned k = (b & 0x80000000u) ? ~b : (b | 0x80000000u);
    unsigned m;
    asm("redux.sync.max.u32 %0, %1, 0xffffffff;" : "=r"(m) : "r"(k));
    unsigned r = (m & 0x80000000u) ? (m & 0x7fffffffu) : ~m;
    return __uint_as_float(r);
}

#define NZ_P   (BATCH * HDIM * HDIM / 4)   // 131072 float4
#define NZ_OUT (NTOK * HDIM / 4)           // 32768 float4

// ---------------------------------------------------------------------------
// Stage 1: zero scratch+out+counter (graph replays), then split-K tiled GEMM
// srcHalf[z][tok, h] = X[tok, kz..kz+384) . W[h, kz..) (+ b[h] in half 0).
// Grid (32 tok-tiles, 4 h-tiles, 2 K-halves) = 256 CTAs. Tile: 8 tok x 128 h,
// K-half 384 in chunks of 64, 128 threads; thread owns 4 h x 2 tokens:
// per k one LDS.128 (w) + one broadcast LDS.64 (x pair) + 8 FMA.
// Consumers (sinkhorn/out) add the two halves on load.
// ---------------------------------------------------------------------------
#define BT    8      // tokens per CTA tile
#define BH    128    // h per CTA tile
#define KC    64     // k-chunk
#define KHALF (DSRC / 2)   // 384
#define WPAD  132    // Ws row stride in floats (128 + 4: LDS.128 phase-clean)
#define STH   128    // src threads
__global__ void __launch_bounds__(STH, 2) src_kernel(
    const float* __restrict__ X, const float* __restrict__ W,
    const float* __restrict__ b, float* __restrict__ out)
{
    const int tid = threadIdx.x;
    const int cta = (blockIdx.z * gridDim.y + blockIdx.y) * gridDim.x
                    + blockIdx.x;                         // 0..255
    // zero g_sumP, d_out, counter (harness poisons d_out)
    {
        float4 z = make_float4(0.f, 0.f, 0.f, 0.f);
        int i0 = cta * STH + tid;
        const int stride = 256 * STH;                     // 32768
#pragma unroll
        for (int i = i0; i < NZ_P + NZ_OUT; i += stride) {
            if (i < NZ_P) reinterpret_cast<float4*>(g_sumP)[i] = z;
            else          reinterpret_cast<float4*>(out)[i - NZ_P] = z;
        }
        if (cta == 0 && tid == 0) g_counter = 0;
    }

    const int tok0 = blockIdx.x * BT;      // gridDim.x = 32
    const int h0   = blockIdx.y * BH;      // gridDim.y = 4
    const int kz   = blockIdx.z * KHALF;   // 0 or 384
    float* dst = blockIdx.z ? g_srcB : g_srcA;

    __shared__ __align__(16) float Ws[KC * WPAD];   // 33 KB, [kk][h]
    __shared__ __align__(16) float Xs[KC * BT];     // 2 KB, [kk][tok]

    const int hq = (tid & 31) * 4;   // 4-h group within tile (0..124)
    const int tp = tid >> 5;         // token-pair index (0..3)
    const int tA = 2 * tp;           // tokens tA, tA+1

    float a0 = 0.f, a1 = 0.f, a2 = 0.f, a3 = 0.f;   // token tA
    float c0 = 0.f, c1 = 0.f, c2 = 0.f, c3 = 0.f;   // token tA+1

    for (int k0 = kz; k0 < kz + KHALF; k0 += KC) {
        __syncthreads();   // protect previous chunk's reads
        // load X tile: 8 tok x 64 k = 512 floats, 4 per thread
        {
            int idx = tid;
#pragma unroll
            for (int r = 0; r < 4; r++, idx += STH) {
                int tt = idx >> 6;         // token 0..7
                int kk = idx & 63;
                Xs[kk * BT + tt] = X[(tok0 + tt) * DSRC + k0 + kk];
            }
        }
        // load+transpose W tile: thread t -> h = t, full 64-k row (16 float4)
        {
            const float4* wsrc = reinterpret_cast<const float4*>(
                W + (size_t)(h0 + tid) * DSRC + k0);
#pragma unroll
            for (int j = 0; j < 16; j++) {
                float4 w4 = wsrc[j];
                int kk = j * 4;
                Ws[(kk + 0) * WPAD + tid] = w4.x;
                Ws[(kk + 1) * WPAD + tid] = w4.y;
                Ws[(kk + 2) * WPAD + tid] = w4.z;
                Ws[(kk + 3) * WPAD + tid] = w4.w;
            }
        }
        __syncthreads();
        // compute: per kk one LDS.128 (w) + one broadcast LDS.64 (x) + 8 FMA
#pragma unroll 8
        for (int kk = 0; kk < KC; kk++) {
            float4 w = *reinterpret_cast<const float4*>(&Ws[kk * WPAD + hq]);
            float2 x = *reinterpret_cast<const float2*>(&Xs[kk * BT + tA]);
            a0 = fmaf(w.x, x.x, a0);
            a1 = fmaf(w.y, x.x, a1);
            a2 = fmaf(w.z, x.x, a2);
            a3 = fmaf(w.w, x.x, a3);
            c0 = fmaf(w.x, x.y, c0);
            c1 = fmaf(w.y, x.y, c1);
            c2 = fmaf(w.z, x.y, c2);
            c3 = fmaf(w.w, x.y, c3);
        }
    }

    float4 bb = make_float4(0.f, 0.f, 0.f, 0.f);
    if (blockIdx.z == 0)
        bb = *reinterpret_cast<const float4*>(&b[h0 + hq]);
    float4 rA = make_float4(a0 + bb.x, a1 + bb.y, a2 + bb.z, a3 + bb.w);
    float4 rB = make_float4(c0 + bb.x, c1 + bb.y, c2 + bb.z, c3 + bb.w);
    *reinterpret_cast<float4*>(&dst[(tok0 + tA) * HDIM + h0 + hq])     = rA;
    *reinterpret_cast<float4*>(&dst[(tok0 + tA + 1) * HDIM + h0 + hq]) = rB;
}

// ---------------------------------------------------------------------------
// Binary search over a sorted float array (u-init only).
// ---------------------------------------------------------------------------
__device__ __forceinline__ int lboundf(const float* __restrict__ A, float x) {
    int lo = 0, hi = HDIM;
    while (lo < hi) { int m = (lo + hi) >> 1; if (A[m] < x) lo = m + 1; else hi = m; }
    return lo;
}

// ---------------------------------------------------------------------------
// One culled half-pass sum with packed f32x2 math; warp-uniform block votes.
// ---------------------------------------------------------------------------
__device__ __forceinline__ float culled_sum(const float4* __restrict__ Q,
                                            const float2* __restrict__ blkRange,
                                            const float* __restrict__ blkMax,
                                            float own, float sh, ull negc2)
{
    const ull own2 = pack2(own, own);
    const ull sh2  = pack2(sh, sh);
    float a0 = 1e-30f, a1 = 0.f;
#pragma unroll 1
    for (int b = 0; b < NBLK; b++) {
        float2 rg = blkRange[b];
        float dd = fmaxf(fmaxf(rg.x - own, own - rg.y), 0.0f);
        bool qual = fmaf(dd * dd, NEGC, blkMax[b] + sh) >= -TW;
        if (__any_sync(0xffffffffu, qual)) {
#pragma unroll
            for (int p = NPAIR * b; p < NPAIR * b + NPAIR; p++) {
                float4 q = Q[p];
                ull X  = pack2(q.x, q.y);
                ull Yd = pack2(q.z, q.w);
                ull d  = subx2(X, own2);
                ull sq = mulx2(d, d);
                ull ys = addx2(Yd, sh2);
                ull e  = fmax2p(sq, negc2, ys);
                float el, eh; unpack2(e, el, eh);
                a0 += ex2(el);
                a1 += ex2(eh);
            }
        }
    }
    return a0 + a1;
}

// ---------------------------------------------------------------------------
// Stage 2: PERSISTENT block-culled per-token base-2 log-domain Sinkhorn.
// Grid 148 CTAs (1/SM); each CTA streams tokens from a global atomic
// counter (work-stealing balances the 256-token load: 1.73 tokens/SM vs
// the 2-CTAs-on-108-SMs imbalance of a 256-CTA launch).
// Per token: joint bitonic sort of s,t (s = srcA+srcB), packed pair arrays,
// 30 iterations of culled shifted-LSE updates, plan accumulation.
// ---------------------------------------------------------------------------
__global__ void __launch_bounds__(512, 2) sinkhorn_kernel(
    const float* __restrict__ Y)
{
    const int tid  = threadIdx.x;
    const int lane = tid & 31;
    const int warp = tid >> 5;

    __shared__ float sVal[HDIM], tVal[HDIM];      // sorted values
    __shared__ int   sIdx[HDIM], tIdx[HDIM];      // sorted pos -> original
    __shared__ __align__(16) float4 SQ[HDIM / 2]; // (s0,s1,v0,v1) pairs
    __shared__ __align__(16) float4 TQ[HDIM / 2]; // (t0,t1,u0,u1) pairs
    __shared__ float2 rgS[NBLK], rgT[NBLK];       // per-block (lo,hi) values
    __shared__ float blkMaxV[NBLK], blkMaxU[NBLK];
    __shared__ int   curTok;

    const ull negc2 = pack2(NEGC, NEGC);
    float* SQ_s = reinterpret_cast<float*>(SQ);
    float* TQ_s = reinterpret_cast<float*>(TQ);
    const int own_slot = (tid >> 1) * 4 + 2 + (tid & 1);

    while (true) {
        if (tid == 0) curTok = atomicAdd(&g_counter, 1);
        __syncthreads();
        const int tok = curTok;
        if (tok >= NTOK) break;
        const int bat = tok >> 7;

        sVal[tid] = g_srcA[tok * HDIM + tid] + g_srcB[tok * HDIM + tid];
        tVal[tid] = Y[tok * HDIM + tid];
        sIdx[tid] = tid;
        tIdx[tid] = tid;
        if (tid < NBLK) blkMaxV[tid] = 0.f;
        __syncthreads();

        // joint bitonic sort of s and t (values + index payloads)
        for (int k = 2; k <= HDIM; k <<= 1) {
            for (int j = k >> 1; j > 0; j >>= 1) {
                int ixj = tid ^ j;
                if (ixj > tid) {
                    bool up = ((tid & k) == 0);
                    float a = sVal[tid], b2 = sVal[ixj];
                    if (up ? (a > b2) : (a < b2)) {
                        sVal[tid] = b2; sVal[ixj] = a;
                        int ti = sIdx[tid]; sIdx[tid] = sIdx[ixj]; sIdx[ixj] = ti;
                    }
                    float c = tVal[tid], d2 = tVal[ixj];
                    if (up ? (c > d2) : (c < d2)) {
                        tVal[tid] = d2; tVal[ixj] = c;
                        int ti = tIdx[tid]; tIdx[tid] = tIdx[ixj]; tIdx[ixj] = ti;
                    }
                }
                __syncthreads();
            }
        }

        // build packed pair arrays + block ranges
        if (tid < HDIM / 2) {
            SQ[tid] = make_float4(sVal[2 * tid], sVal[2 * tid + 1], 0.f, 0.f);
            TQ[tid] = make_float4(tVal[2 * tid], tVal[2 * tid + 1], 0.f, 0.f);
        }
        if (tid < NBLK) {
            rgS[tid] = make_float2(sVal[BSZ * tid], sVal[BSZ * tid + BSZ - 1]);
            rgT[tid] = make_float2(tVal[BSZ * tid], tVal[BSZ * tid + BSZ - 1]);
        }
        __syncthreads();

        const float t_own = tVal[tid];
        const float s_own = sVal[tid];
        const int   jorig = tIdx[tid];

        // init u via nearest sorted s neighbor: u = -9 + C*d_nn^2
        float u_own;
        {
            int p = lboundf(sVal, t_own);
            float dn = 3.402823466e+38f;
            if (p < HDIM) dn = fabsf(sVal[p] - t_own);
            if (p > 0)    dn = fminf(dn, fabsf(sVal[p - 1] - t_own));
            u_own = LOGMARG2 + CPOS * dn * dn;
        }
        float v_own = 0.f;

        for (int it = 0; it < NITER; it++) {
            // ---- u-pass ----
            u_own -= lg2(culled_sum(SQ, rgS, blkMaxV, t_own, u_own + 9.0f, negc2));
            TQ_s[own_slot] = u_own;
            {
                float m = warp_max_f32(u_own);
                if (lane == 0) blkMaxU[warp] = m;
            }
            __syncthreads();

            // ---- v-pass ----
            v_own -= lg2(culled_sum(TQ, rgT, blkMaxU, s_own, v_own + 9.0f, negc2));
            SQ_s[own_slot] = v_own;
            {
                float m = warp_max_f32(v_own);
                if (lane == 0) blkMaxV[warp] = m;
            }
            __syncthreads();
        }

        // ---- Plan accumulation ----
        {
            float* rowdst = g_sumP + (size_t)bat * HDIM * HDIM + (size_t)jorig * HDIM;
            const float sh = u_own + 9.0f;
            const ull own2 = pack2(t_own, t_own);
            const ull sh2  = pack2(sh, sh);
#pragma unroll 1
            for (int b = 0; b < NBLK; b++) {
                float2 rg = rgS[b];
                float dd = fmaxf(fmaxf(rg.x - t_own, t_own - rg.y), 0.0f);
                bool qual = fmaf(dd * dd, NEGC, blkMaxV[b] + sh) >= -31.0f;
                if (__any_sync(0xffffffffu, qual)) {
#pragma unroll 4
                    for (int p = NPAIR * b; p < NPAIR * b + NPAIR; p++) {
                        float4 q = SQ[p];
                        ull X  = pack2(q.x, q.y);
                        ull Yd = pack2(q.z, q.w);
                        ull d  = subx2(X, own2);
                        ull sq = mulx2(d, d);
                        ull ys = addx2(Yd, sh2);
                        ull e  = fmax2p(sq, negc2, ys);
                        float el, eh; unpack2(e, el, eh);
                        if (el > -31.f) atomicAdd(rowdst + sIdx[2 * p],     ex2(el - 9.0f));
                        if (eh > -31.f) atomicAdd(rowdst + sIdx[2 * p + 1], ex2(eh - 9.0f));
                    }
                }
            }
        }
        __syncthreads();   // smem reuse barrier before next token
    }
}

// ---------------------------------------------------------------------------
// Stage 3: out[tok, k] += sum_{h in slice} src[tok,h]*(sumP[b,h,k]*2000
//                                                      + delta[h,k])
// Grid (16 token-groups of 16, 16 h-slices of 32). 256 CTAs, 256 threads.
// ---------------------------------------------------------------------------
#define OT_TOK 16
#define OT_H   32
__global__ void __launch_bounds__(256) out_kernel(
    const float* __restrict__ delta, float* __restrict__ out)
{
    const int tok0 = blockIdx.x * OT_TOK;
    const int h0   = blockIdx.y * OT_H;
    const int bat  = tok0 >> 7;       // OT_TOK divides SEQ -> no straddle
    const int k2   = threadIdx.x;     // float2 column index (0..255)

    __shared__ float sr[OT_TOK][OT_H];   // 2 KB
    for (int idx = threadIdx.x; idx < OT_TOK * OT_H; idx += 256) {
        int g = (tok0 + idx / OT_H) * HDIM + h0 + idx % OT_H;
        sr[idx / OT_H][idx % OT_H] = g_srcA[g] + g_srcB[g];
    }
    __syncthreads();

    const float2* P2 = reinterpret_cast<const float2*>(
        g_sumP + (size_t)bat * HDIM * HDIM);
    const float2* D2 = reinterpret_cast<const float2*>(delta);

    float a0[OT_TOK], a1[OT_TOK];
#pragma unroll
    for (int t = 0; t < OT_TOK; t++) { a0[t] = 0.f; a1[t] = 0.f; }

#pragma unroll 4
    for (int h = 0; h < OT_H; h++) {
        float2 p = __ldg(&P2[(h0 + h) * 256 + k2]);
        float2 d = __ldg(&D2[(h0 + h) * 256 + k2]);
        float pv0 = fmaf(p.x, 2000.0f, d.x);
        float pv1 = fmaf(p.y, 2000.0f, d.y);
#pragma unroll
        for (int t = 0; t < OT_TOK; t++) {
            float s = sr[t][h];
            a0[t] = fmaf(s, pv0, a0[t]);
            a1[t] = fmaf(s, pv1, a1[t]);
        }
    }
#pragma unroll
    for (int t = 0; t < OT_TOK; t++) {
        atomicAdd(&out[(tok0 + t) * HDIM + 2 * k2],     a0[t]);
        atomicAdd(&out[(tok0 + t) * HDIM + 2 * k2 + 1], a1[t]);
    }
}

// ---------------------------------------------------------------------------
extern "C" void kernel_launch(void* const* d_in, const int* in_sizes, int n_in,
                              void* d_out, int out_size)
{
    const float* X     = (const float*)d_in[0];  // (2,128,768)
    const float* Y     = (const float*)d_in[1];  // (2,128,512)
    const float* W     = (const float*)d_in[2];  // (512,768)
    const float* b     = (const float*)d_in[3];  // (512)
    const float* delta = (const float*)d_in[4];  // (512,512)
    float* out = (float*)d_out;                  // (2,128,512)

    dim3 sgrid(NTOK / BT, HDIM / BH, 2);         // (32, 4, 2) = 256 CTAs
    src_kernel<<<sgrid, STH>>>(X, W, b, out);
    sinkhorn_kernel<<<NSM, 512>>>(Y);
    dim3 ogrid(NTOK / OT_TOK, HDIM / OT_H);
    out_kernel<<<ogrid, 256>>>(delta, out);
}